// round 1
// baseline (speedup 1.0000x reference)
#include <cuda_runtime.h>
#include <cstdint>

#define EPSF 1e-5f
#define QBF  127.0f

static constexpr int MTOK  = 4 * 4096;   // tokens
static constexpr int DIN   = 1024;
static constexpr int INNER = 4096;

// ---------------- device scratch (no allocations allowed) ----------------
__device__ float  g_wfac[2];                         // clip(mean|w|, eps) per weight
__device__ float  g_part[2][512];                    // partial |w| sums
__device__ int8_t g_w1q[(size_t)INNER * DIN];        // ternary w1
__device__ int8_t g_w2q[(size_t)DIN * INNER];        // ternary w2
__device__ int8_t g_xq [(size_t)MTOK * DIN];         // quantized layer-1 input
__device__ float  g_sx [MTOK];                       // per-token dequant factor (layer 1)
__device__ float  g_h  [(size_t)MTOK * INNER];       // fp32 hidden (gelu output)
__device__ int8_t g_hq [(size_t)MTOK * INNER];       // quantized layer-2 input
__device__ float  g_sh [MTOK];                       // per-token dequant factor (layer 2)

// ---------------- weight absmean: pass 1 (deterministic partials) --------
__global__ void wabs_part(const float* __restrict__ w, int n, int slot) {
    float s = 0.f;
    const float4* w4 = (const float4*)w;
    int nv = n >> 2;
    for (int i = blockIdx.x * blockDim.x + threadIdx.x; i < nv;
         i += gridDim.x * blockDim.x) {
        float4 v = w4[i];
        s += fabsf(v.x) + fabsf(v.y) + fabsf(v.z) + fabsf(v.w);
    }
    __shared__ float sh[256];
    sh[threadIdx.x] = s;
    __syncthreads();
    for (int o = 128; o > 0; o >>= 1) {
        if (threadIdx.x < o) sh[threadIdx.x] += sh[threadIdx.x + o];
        __syncthreads();
    }
    if (threadIdx.x == 0) g_part[slot][blockIdx.x] = sh[0];
}

// ---------------- weight absmean: pass 2 (single block) ------------------
__global__ void wfinal(int n1, int n2) {
    __shared__ float sh[256];
    for (int slot = 0; slot < 2; slot++) {
        float s = g_part[slot][threadIdx.x] + g_part[slot][threadIdx.x + 256];
        sh[threadIdx.x] = s;
        __syncthreads();
        for (int o = 128; o > 0; o >>= 1) {
            if (threadIdx.x < o) sh[threadIdx.x] += sh[threadIdx.x + o];
            __syncthreads();
        }
        if (threadIdx.x == 0) {
            float mean = sh[0] / (float)(slot ? n2 : n1);
            g_wfac[slot] = fmaxf(mean, EPSF);
        }
        __syncthreads();
    }
}

// ---------------- ternary weight quantization ----------------------------
__global__ void wquant(const float* __restrict__ w, int n, int slot) {
    int i = blockIdx.x * blockDim.x + threadIdx.x;
    int nv = n >> 2;
    if (i >= nv) return;
    float sc = 1.f / g_wfac[slot];     // scale = 1/clip(mean,eps)
    float4 v = ((const float4*)w)[i];
    int8_t* q = slot ? g_w2q : g_w1q;
    char4 o;
    int t;
    t = (int)rintf(v.x * sc); t = t < -1 ? -1 : (t > 1 ? 1 : t); o.x = (int8_t)t;
    t = (int)rintf(v.y * sc); t = t < -1 ? -1 : (t > 1 ? 1 : t); o.y = (int8_t)t;
    t = (int)rintf(v.z * sc); t = t < -1 ? -1 : (t > 1 ? 1 : t); o.z = (int8_t)t;
    t = (int)rintf(v.w * sc); t = t < -1 ? -1 : (t > 1 ? 1 : t); o.w = (int8_t)t;
    ((char4*)q)[i] = o;
}

// ---------------- per-token rmsnorm + absmax int8 quant ------------------
// slot 0: X = x (param), D=1024 -> g_xq/g_sx
// slot 1: X = g_h,       D=4096 -> g_hq/g_sh
__global__ void act_quant(const float* __restrict__ xin, int slot) {
    const int D = slot ? INNER : DIN;
    const float* X = slot ? g_h : xin;
    int8_t* Q      = slot ? g_hq : g_xq;
    float* inv     = slot ? g_sh : g_sx;

    int m = blockIdx.x;
    const float4* xr = (const float4*)(X + (size_t)m * D);
    int nv = D >> 2;

    float ss = 0.f, am = 0.f;
    for (int v = threadIdx.x; v < nv; v += blockDim.x) {
        float4 f = xr[v];
        ss += f.x * f.x + f.y * f.y + f.z * f.z + f.w * f.w;
        am = fmaxf(am, fmaxf(fmaxf(fabsf(f.x), fabsf(f.y)),
                             fmaxf(fabsf(f.z), fabsf(f.w))));
    }
    __shared__ float shs[256], sha[256];
    shs[threadIdx.x] = ss;
    sha[threadIdx.x] = am;
    __syncthreads();
    for (int o = 128; o > 0; o >>= 1) {
        if (threadIdx.x < o) {
            shs[threadIdx.x] += shs[threadIdx.x + o];
            sha[threadIdx.x] = fmaxf(sha[threadIdx.x], sha[threadIdx.x + o]);
        }
        __syncthreads();
    }
    __shared__ float s_rn, s_sc;
    if (threadIdx.x == 0) {
        float rn  = rsqrtf(shs[0] / (float)D + EPSF);  // rmsnorm factor
        float amn = fmaxf(sha[0] * rn, EPSF);          // absmax of normalized row
        s_rn = rn;
        s_sc = QBF / amn;
        inv[m] = amn / QBF;                            // dequant factor
    }
    __syncthreads();
    float rn = s_rn, sc = s_sc;

    char4* qr = (char4*)(Q + (size_t)m * D);
    for (int v = threadIdx.x; v < nv; v += blockDim.x) {
        float4 f = xr[v];
        char4 o;
        int t;
        // two-step multiply to match reference rounding path (xn then xn*scale)
        t = (int)rintf((f.x * rn) * sc); t = t < -128 ? -128 : (t > 127 ? 127 : t); o.x = (int8_t)t;
        t = (int)rintf((f.y * rn) * sc); t = t < -128 ? -128 : (t > 127 ? 127 : t); o.y = (int8_t)t;
        t = (int)rintf((f.z * rn) * sc); t = t < -128 ? -128 : (t > 127 ? 127 : t); o.z = (int8_t)t;
        t = (int)rintf((f.w * rn) * sc); t = t < -128 ? -128 : (t > 127 ? 127 : t); o.w = (int8_t)t;
        qr[v] = o;
    }
}

// ---------------- int8 GEMM (dp4a), fused dequant/bias/gelu --------------
// layer 0: out = gelu(xq @ w1q^T * sx*sw1 + b1) -> g_h      (M=MTOK,N=INNER,K=DIN)
// layer 1: out =      hq @ w2q^T * sh*sw2 + b2  -> d_out    (M=MTOK,N=DIN,K=INNER)
#define GBM 128
#define GBN 128

__global__ __launch_bounds__(256)
void gemm_s8(const float* __restrict__ bias, float* __restrict__ dout, int layer) {
    const int8_t* A;
    const int8_t* B;
    const float* inva;
    float* out;
    int N, K;
    if (layer == 0) {
        A = g_xq; B = g_w1q; inva = g_sx; out = g_h;  N = INNER; K = DIN;
    } else {
        A = g_hq; B = g_w2q; inva = g_sh; out = dout; N = DIN;   K = INNER;
    }

    __shared__ int As[16][GBM];   // k-major: As[kword][row]
    __shared__ int Bs[16][GBN];

    int tid = threadIdx.x;
    int ty = tid >> 4, tx = tid & 15;
    const int m0 = blockIdx.y * GBM;
    const int n0 = blockIdx.x * GBN;

    int acc[8][8];
#pragma unroll
    for (int i = 0; i < 8; i++)
#pragma unroll
        for (int j = 0; j < 8; j++) acc[i][j] = 0;

    const int kv = K >> 4;  // uint4 per row
    const uint4* Ag = (const uint4*)(A + (size_t)m0 * K);
    const uint4* Bg = (const uint4*)(B + (size_t)n0 * K);

    for (int kt = 0; kt < kv; kt += 4) {  // 64 bytes of K per tile
#pragma unroll
        for (int it = 0; it < 2; it++) {
            int li  = tid + it * 256;   // 0..511
            int row = li >> 2;          // 0..127
            int ch  = li & 3;           // 16B chunk
            uint4 va = Ag[(size_t)row * kv + kt + ch];
            As[ch * 4 + 0][row] = (int)va.x;
            As[ch * 4 + 1][row] = (int)va.y;
            As[ch * 4 + 2][row] = (int)va.z;
            As[ch * 4 + 3][row] = (int)va.w;
            uint4 vb = Bg[(size_t)row * kv + kt + ch];
            Bs[ch * 4 + 0][row] = (int)vb.x;
            Bs[ch * 4 + 1][row] = (int)vb.y;
            Bs[ch * 4 + 2][row] = (int)vb.z;
            Bs[ch * 4 + 3][row] = (int)vb.w;
        }
        __syncthreads();
#pragma unroll
        for (int kk = 0; kk < 16; kk++) {
            int a[8], b[8];
            *(uint4*)&a[0] = *(const uint4*)&As[kk][ty * 8];
            *(uint4*)&a[4] = *(const uint4*)&As[kk][ty * 8 + 4];
            *(uint4*)&b[0] = *(const uint4*)&Bs[kk][tx * 8];
            *(uint4*)&b[4] = *(const uint4*)&Bs[kk][tx * 8 + 4];
#pragma unroll
            for (int i = 0; i < 8; i++)
#pragma unroll
                for (int j = 0; j < 8; j++)
                    acc[i][j] = __dp4a(a[i], b[j], acc[i][j]);
        }
        __syncthreads();
    }

    // epilogue: exact dequant (int32 accumulation is exact), bias, optional gelu
    float fw = g_wfac[layer];
#pragma unroll
    for (int i = 0; i < 8; i++) {
        int m = m0 + ty * 8 + i;
        float fa = inva[m] * fw;
        float vbuf[8];
#pragma unroll
        for (int j = 0; j < 8; j++) {
            int n = n0 + tx * 8 + j;
            float v = (float)acc[i][j] * fa + bias[n];
            if (layer == 0)
                v = 0.5f * v * (1.f + erff(v * 0.70710678118654752f));  // exact gelu
            vbuf[j] = v;
        }
        float4* op = (float4*)(out + (size_t)m * N + n0 + tx * 8);
        op[0] = make_float4(vbuf[0], vbuf[1], vbuf[2], vbuf[3]);
        op[1] = make_float4(vbuf[4], vbuf[5], vbuf[6], vbuf[7]);
    }
}

// -------------------------------------------------------------------------
extern "C" void kernel_launch(void* const* d_in, const int* in_sizes, int n_in,
                              void* d_out, int out_size) {
    const float* x  = (const float*)d_in[0];   // [4,4096,1024]
    const float* w1 = (const float*)d_in[1];   // [4096,1024]
    const float* b1 = (const float*)d_in[2];   // [4096]
    const float* w2 = (const float*)d_in[3];   // [1024,4096]
    const float* b2 = (const float*)d_in[4];   // [1024]
    float* out = (float*)d_out;                // [4,4096,1024]

    const int n1 = INNER * DIN;   // 4,194,304
    const int n2 = DIN * INNER;

    // 1) weight absmean (deterministic two-pass)
    wabs_part<<<512, 256>>>(w1, n1, 0);
    wabs_part<<<512, 256>>>(w2, n2, 1);
    wfinal<<<1, 256>>>(n1, n2);

    // 2) ternary weight quant
    wquant<<<(n1 / 4 + 255) / 256, 256>>>(w1, n1, 0);
    wquant<<<(n2 / 4 + 255) / 256, 256>>>(w2, n2, 1);

    // 3) layer-1 activation quant (rmsnorm + absmax int8)
    act_quant<<<MTOK, 256>>>(x, 0);

    // 4) GEMM1 + gelu -> g_h
    gemm_s8<<<dim3(INNER / GBN, MTOK / GBM), 256>>>(b1, nullptr, 0);

    // 5) layer-2 activation quant
    act_quant<<<MTOK, 256>>>(nullptr, 1);

    // 6) GEMM2 -> out
    gemm_s8<<<dim3(DIN / GBN, MTOK / GBM), 256>>>(b2, out, 1);
}

// round 3
// speedup vs baseline: 1.1584x; 1.1584x over previous
#include <cuda_runtime.h>
#include <cstdint>

#define EPSF 1e-5f
#define QBF  127.0f

static constexpr int MTOK  = 4 * 4096;
static constexpr int DIN   = 1024;
static constexpr int INNER = 4096;

// ---------------- device scratch ----------------
__device__ float  g_wfac[2];
__device__ float  g_part[2][512];
__device__ __align__(16) int8_t g_w1q[(size_t)INNER * DIN];
__device__ __align__(16) int8_t g_w2q[(size_t)DIN * INNER];
__device__ __align__(16) int8_t g_xq [(size_t)MTOK * DIN];
__device__ float  g_sx[MTOK];
__device__ __align__(16) float  g_h [(size_t)MTOK * INNER];
__device__ __align__(16) int8_t g_hq[(size_t)MTOK * INNER];
__device__ float  g_sh[MTOK];

// ---------------- helpers ----------------
__device__ __forceinline__ uint32_t smem_u32(const void* p) {
    uint32_t a;
    asm("{ .reg .u64 t; cvta.to.shared.u64 t, %1; cvt.u32.u64 %0, t; }" : "=r"(a) : "l"(p));
    return a;
}
__device__ __forceinline__ void cp_async16(uint32_t dst, const void* src) {
    asm volatile("cp.async.cg.shared.global [%0], [%1], 16;" :: "r"(dst), "l"(src) : "memory");
}
#define CP_COMMIT()  asm volatile("cp.async.commit_group;" ::: "memory")
#define CP_WAIT(N)   asm volatile("cp.async.wait_group %0;" :: "n"(N) : "memory")

__device__ __forceinline__ void ldmx4(uint32_t& r0, uint32_t& r1, uint32_t& r2, uint32_t& r3,
                                      uint32_t addr) {
    asm volatile("ldmatrix.sync.aligned.m8n8.x4.shared.b16 {%0,%1,%2,%3}, [%4];"
                 : "=r"(r0), "=r"(r1), "=r"(r2), "=r"(r3) : "r"(addr));
}
__device__ __forceinline__ void mma_s8(int* c, const uint32_t* a, const uint32_t* b) {
    asm volatile("mma.sync.aligned.m16n8k32.row.col.s32.s8.s8.s32 "
                 "{%0,%1,%2,%3}, {%4,%5,%6,%7}, {%8,%9}, {%0,%1,%2,%3};"
                 : "+r"(c[0]), "+r"(c[1]), "+r"(c[2]), "+r"(c[3])
                 : "r"(a[0]), "r"(a[1]), "r"(a[2]), "r"(a[3]), "r"(b[0]), "r"(b[1]));
}

// ---------------- weight absmean ----------------
__global__ void wabs_part(const float* __restrict__ w, int n, int slot) {
    float s = 0.f;
    const float4* w4 = (const float4*)w;
    int nv = n >> 2;
    for (int i = blockIdx.x * blockDim.x + threadIdx.x; i < nv; i += gridDim.x * blockDim.x) {
        float4 v = w4[i];
        s += fabsf(v.x) + fabsf(v.y) + fabsf(v.z) + fabsf(v.w);
    }
    __shared__ float sh[256];
    sh[threadIdx.x] = s;
    __syncthreads();
    for (int o = 128; o > 0; o >>= 1) {
        if (threadIdx.x < o) sh[threadIdx.x] += sh[threadIdx.x + o];
        __syncthreads();
    }
    if (threadIdx.x == 0) g_part[slot][blockIdx.x] = sh[0];
}

__global__ void wfinal(int n1, int n2) {
    __shared__ float sh[256];
    for (int slot = 0; slot < 2; slot++) {
        float s = g_part[slot][threadIdx.x] + g_part[slot][threadIdx.x + 256];
        sh[threadIdx.x] = s;
        __syncthreads();
        for (int o = 128; o > 0; o >>= 1) {
            if (threadIdx.x < o) sh[threadIdx.x] += sh[threadIdx.x + o];
            __syncthreads();
        }
        if (threadIdx.x == 0) g_wfac[slot] = fmaxf(sh[0] / (float)(slot ? n2 : n1), EPSF);
        __syncthreads();
    }
}

// ---------------- ternary weight quant ----------------
__global__ void wquant(const float* __restrict__ w, int n, int slot) {
    int i = blockIdx.x * blockDim.x + threadIdx.x;
    int nv = n >> 2;
    if (i >= nv) return;
    float sc = 1.f / g_wfac[slot];
    float4 v = ((const float4*)w)[i];
    int8_t* q = slot ? g_w2q : g_w1q;
    char4 o;
    int t;
    t = (int)rintf(v.x * sc); t = t < -1 ? -1 : (t > 1 ? 1 : t); o.x = (int8_t)t;
    t = (int)rintf(v.y * sc); t = t < -1 ? -1 : (t > 1 ? 1 : t); o.y = (int8_t)t;
    t = (int)rintf(v.z * sc); t = t < -1 ? -1 : (t > 1 ? 1 : t); o.z = (int8_t)t;
    t = (int)rintf(v.w * sc); t = t < -1 ? -1 : (t > 1 ? 1 : t); o.w = (int8_t)t;
    ((char4*)q)[i] = o;
}

// ---------------- rmsnorm + absmax int8 quant ----------------
__global__ void act_quant(const float* __restrict__ xin, int slot) {
    const int D = slot ? INNER : DIN;
    const float* X = slot ? g_h : xin;
    int8_t* Q      = slot ? g_hq : g_xq;
    float* inv     = slot ? g_sh : g_sx;

    int m = blockIdx.x;
    const float4* xr = (const float4*)(X + (size_t)m * D);
    int nv = D >> 2;

    float ss = 0.f, am = 0.f;
    for (int v = threadIdx.x; v < nv; v += blockDim.x) {
        float4 f = xr[v];
        ss += f.x * f.x + f.y * f.y + f.z * f.z + f.w * f.w;
        am = fmaxf(am, fmaxf(fmaxf(fabsf(f.x), fabsf(f.y)), fmaxf(fabsf(f.z), fabsf(f.w))));
    }
    __shared__ float shs[256], sha[256];
    shs[threadIdx.x] = ss;
    sha[threadIdx.x] = am;
    __syncthreads();
    for (int o = 128; o > 0; o >>= 1) {
        if (threadIdx.x < o) {
            shs[threadIdx.x] += shs[threadIdx.x + o];
            sha[threadIdx.x] = fmaxf(sha[threadIdx.x], sha[threadIdx.x + o]);
        }
        __syncthreads();
    }
    __shared__ float s_rn, s_sc;
    if (threadIdx.x == 0) {
        float rn = rsqrtf(shs[0] / (float)D + EPSF);
        float amn = fmaxf(sha[0] * rn, EPSF);
        s_rn = rn;
        s_sc = QBF / amn;
        inv[m] = amn / QBF;
    }
    __syncthreads();
    float rn = s_rn, sc = s_sc;

    char4* qr = (char4*)(Q + (size_t)m * D);
    for (int v = threadIdx.x; v < nv; v += blockDim.x) {
        float4 f = xr[v];
        char4 o;
        int t;
        t = (int)rintf((f.x * rn) * sc); t = t < -128 ? -128 : (t > 127 ? 127 : t); o.x = (int8_t)t;
        t = (int)rintf((f.y * rn) * sc); t = t < -128 ? -128 : (t > 127 ? 127 : t); o.y = (int8_t)t;
        t = (int)rintf((f.z * rn) * sc); t = t < -128 ? -128 : (t > 127 ? 127 : t); o.z = (int8_t)t;
        t = (int)rintf((f.w * rn) * sc); t = t < -128 ? -128 : (t > 127 ? 127 : t); o.w = (int8_t)t;
        qr[v] = o;
    }
}

// ---------------- IMMA GEMM: tile 128x128, K-stage 128 bytes ----------------
// layer 0: g_h = gelu(xq @ w1q^T * sx*fw1 + b1)   M=MTOK, N=INNER, K=DIN
// layer 1: out =      hq @ w2q^T * sh*fw2 + b2    M=MTOK, N=DIN,   K=INNER
static constexpr int BM = 128, BN = 128, BK = 128;
static constexpr int STAGE_BYTES = BM * BK + BN * BK;       // 32 KB
static constexpr int SMEM_BYTES  = 2 * STAGE_BYTES;          // 64 KB

__device__ __forceinline__ uint32_t swz(uint32_t row, uint32_t kb) {
    // SW128 swizzle, row stride 128B: bits[6:4] ^= row[2:0]
    return row * 128u + (kb ^ ((row & 7u) << 4));
}

__global__ __launch_bounds__(256)
void gemm_imma(const float* __restrict__ bias, float* __restrict__ dout, int layer) {
    const int8_t *A, *B;
    const float* inva;
    float* out;
    int N, K;
    if (layer == 0) { A = g_xq; B = g_w1q; inva = g_sx; out = g_h;  N = INNER; K = DIN;  }
    else            { A = g_hq; B = g_w2q; inva = g_sh; out = dout; N = DIN;   K = INNER; }

    extern __shared__ char smem[];
    const uint32_t sb = smem_u32(smem);

    const int tid = threadIdx.x;
    const int wid = tid >> 5, lid = tid & 31;
    const int wm = wid >> 1, wn = wid & 1;          // 4 x 2 warp grid
    const int m0 = blockIdx.y * BM;
    const int n0 = blockIdx.x * BN;

    // ----- global load lane mapping: 4 chunks A + 4 chunks B per thread -----
    // chunk c in [0,1024): row = c>>3, ch = c&7 (16B each)
    const int lrow = tid >> 1;                 // handles rows: lrow, lrow+? -> use c = tid + t*256
    (void)lrow;

    int acc[2][8][4];
#pragma unroll
    for (int i = 0; i < 2; i++)
#pragma unroll
        for (int j = 0; j < 8; j++)
#pragma unroll
            for (int q = 0; q < 4; q++) acc[i][j][q] = 0;

    const int nk = K / BK;

    // ----- ldmatrix lane-invariant address components -----
    const int ltile = lid >> 3, lr = lid & 7;
    const uint32_t khalf = (ltile >> 1) * 16;     // 0 or 16
    uint32_t a_off[2], a_xor[2];
#pragma unroll
    for (int i = 0; i < 2; i++) {
        uint32_t row = wm * 32 + i * 16 + (ltile & 1) * 8 + lr;
        a_off[i] = row * 128u;
        a_xor[i] = (row & 7u) << 4;
    }
    uint32_t b_off[4], b_xor[4];
#pragma unroll
    for (int jp = 0; jp < 4; jp++) {
        uint32_t row = wn * 64 + jp * 16 + (ltile & 1) * 8 + lr;
        b_off[jp] = row * 128u;
        b_xor[jp] = (row & 7u) << 4;
    }

    auto load_stage = [&](int buf, int c) {
        uint32_t baseA = sb + buf * STAGE_BYTES;
        uint32_t baseB = baseA + BM * BK;
        const int8_t* Ap = A + (size_t)m0 * K + c * BK;
        const int8_t* Bp = B + (size_t)n0 * K + c * BK;
#pragma unroll
        for (int t = 0; t < 4; t++) {
            int ci = tid + t * 256;
            uint32_t row = ci >> 3, ch = (ci & 7) * 16;
            cp_async16(baseA + swz(row, ch), Ap + (size_t)row * K + ch);
        }
#pragma unroll
        for (int t = 0; t < 4; t++) {
            int ci = tid + t * 256;
            uint32_t row = ci >> 3, ch = (ci & 7) * 16;
            cp_async16(baseB + swz(row, ch), Bp + (size_t)row * K + ch);
        }
        CP_COMMIT();
    };

    load_stage(0, 0);

    for (int c = 0; c < nk; c++) {
        if (c + 1 < nk) {
            load_stage((c + 1) & 1, c + 1);
            CP_WAIT(1);
        } else {
            CP_WAIT(0);
        }
        __syncthreads();

        uint32_t baseA = sb + (c & 1) * STAGE_BYTES;
        uint32_t baseB = baseA + BM * BK;

#pragma unroll
        for (int kk = 0; kk < BK; kk += 32) {
            uint32_t kb = kk + khalf;
            uint32_t afr[2][4];
#pragma unroll
            for (int i = 0; i < 2; i++)
                ldmx4(afr[i][0], afr[i][1], afr[i][2], afr[i][3],
                      baseA + a_off[i] + (kb ^ a_xor[i]));
            uint32_t bfr[8][2];
#pragma unroll
            for (int jp = 0; jp < 4; jp++) {
                uint32_t r0, r1, r2, r3;
                ldmx4(r0, r1, r2, r3, baseB + b_off[jp] + (kb ^ b_xor[jp]));
                bfr[jp * 2 + 0][0] = r0; bfr[jp * 2 + 0][1] = r2;
                bfr[jp * 2 + 1][0] = r1; bfr[jp * 2 + 1][1] = r3;
            }
#pragma unroll
            for (int i = 0; i < 2; i++)
#pragma unroll
                for (int j = 0; j < 8; j++)
                    mma_s8(acc[i][j], afr[i], bfr[j]);
        }
        __syncthreads();
    }

    // ----- epilogue: dequant + bias (+ exact gelu for layer 0) -----
    const float fw = g_wfac[layer];
    const int g = lid >> 2, tig = lid & 3;
#pragma unroll
    for (int i = 0; i < 2; i++) {
        int r0 = m0 + wm * 32 + i * 16 + g;
        float fa0 = inva[r0] * fw;
        float fa1 = inva[r0 + 8] * fw;
#pragma unroll
        for (int j = 0; j < 8; j++) {
            int n = n0 + wn * 64 + j * 8 + tig * 2;
            float bx = bias[n], by = bias[n + 1];
            float v0 = (float)acc[i][j][0] * fa0 + bx;
            float v1 = (float)acc[i][j][1] * fa0 + by;
            float v2 = (float)acc[i][j][2] * fa1 + bx;
            float v3 = (float)acc[i][j][3] * fa1 + by;
            if (layer == 0) {
                v0 = 0.5f * v0 * (1.f + erff(v0 * 0.70710678118654752f));
                v1 = 0.5f * v1 * (1.f + erff(v1 * 0.70710678118654752f));
                v2 = 0.5f * v2 * (1.f + erff(v2 * 0.70710678118654752f));
                v3 = 0.5f * v3 * (1.f + erff(v3 * 0.70710678118654752f));
            }
            *(float2*)(out + (size_t)r0 * N + n)       = make_float2(v0, v1);
            *(float2*)(out + (size_t)(r0 + 8) * N + n) = make_float2(v2, v3);
        }
    }
}

// -------------------------------------------------------------------------
extern "C" void kernel_launch(void* const* d_in, const int* in_sizes, int n_in,
                              void* d_out, int out_size) {
    const float* x  = (const float*)d_in[0];
    const float* w1 = (const float*)d_in[1];
    const float* b1 = (const float*)d_in[2];
    const float* w2 = (const float*)d_in[3];
    const float* b2 = (const float*)d_in[4];
    float* out = (float*)d_out;

    const int n1 = INNER * DIN;
    const int n2 = DIN * INNER;

    cudaFuncSetAttribute(gemm_imma, cudaFuncAttributeMaxDynamicSharedMemorySize, SMEM_BYTES);

    wabs_part<<<512, 256>>>(w1, n1, 0);
    wabs_part<<<512, 256>>>(w2, n2, 1);
    wfinal<<<1, 256>>>(n1, n2);

    wquant<<<(n1 / 4 + 255) / 256, 256>>>(w1, n1, 0);
    wquant<<<(n2 / 4 + 255) / 256, 256>>>(w2, n2, 1);

    act_quant<<<MTOK, 256>>>(x, 0);
    gemm_imma<<<dim3(INNER / BN, MTOK / BM), 256, SMEM_BYTES>>>(b1, nullptr, 0);
    act_quant<<<MTOK, 256>>>(nullptr, 1);
    gemm_imma<<<dim3(DIN / BN, MTOK / BM), 256, SMEM_BYTES>>>(b2, out, 1);
}

// round 4
// speedup vs baseline: 2.8665x; 2.4747x over previous
#include <cuda_runtime.h>
#include <cuda_bf16.h>
#include <cstdint>

#define EPSF 1e-5f
#define QBF  127.0f

static constexpr int MTOK  = 4 * 4096;
static constexpr int DIN   = 1024;
static constexpr int INNER = 4096;

// ---------------- device scratch ----------------
__device__ float g_wfac[2];
__device__ float g_part[2][256];
__device__ __align__(16) __nv_bfloat16 g_w1q[(size_t)INNER * DIN];
__device__ __align__(16) __nv_bfloat16 g_w2q[(size_t)DIN * INNER];
__device__ __align__(16) __nv_bfloat16 g_xq [(size_t)MTOK * DIN];
__device__ float g_sx[MTOK];
__device__ __align__(16) float g_h [(size_t)MTOK * INNER];
__device__ __align__(16) __nv_bfloat16 g_hq[(size_t)MTOK * INNER];
__device__ float g_sh[MTOK];

// ---------------- helpers ----------------
__device__ __forceinline__ uint32_t smem_u32(const void* p) {
    uint32_t a;
    asm("{ .reg .u64 t; cvta.to.shared.u64 t, %1; cvt.u32.u64 %0, t; }" : "=r"(a) : "l"(p));
    return a;
}
__device__ __forceinline__ void cp_async16(uint32_t dst, const void* src) {
    asm volatile("cp.async.cg.shared.global [%0], [%1], 16;" :: "r"(dst), "l"(src) : "memory");
}
#define CP_COMMIT()  asm volatile("cp.async.commit_group;" ::: "memory")
#define CP_WAIT(N)   asm volatile("cp.async.wait_group %0;" :: "n"(N) : "memory")

__device__ __forceinline__ void ldmx4(uint32_t& r0, uint32_t& r1, uint32_t& r2, uint32_t& r3,
                                      uint32_t addr) {
    asm volatile("ldmatrix.sync.aligned.m8n8.x4.shared.b16 {%0,%1,%2,%3}, [%4];"
                 : "=r"(r0), "=r"(r1), "=r"(r2), "=r"(r3) : "r"(addr));
}
__device__ __forceinline__ void mma_bf16(float* c, const uint32_t* a, const uint32_t* b) {
    asm volatile("mma.sync.aligned.m16n8k16.row.col.f32.bf16.bf16.f32 "
                 "{%0,%1,%2,%3}, {%4,%5,%6,%7}, {%8,%9}, {%0,%1,%2,%3};"
                 : "+f"(c[0]), "+f"(c[1]), "+f"(c[2]), "+f"(c[3])
                 : "r"(a[0]), "r"(a[1]), "r"(a[2]), "r"(a[3]), "r"(b[0]), "r"(b[1]));
}

// ---------------- weight absmean (both weights in one launch) ------------
__global__ void wabs_part(const float* __restrict__ w1, const float* __restrict__ w2,
                          int n) {
    int slot = blockIdx.y;
    const float4* w4 = (const float4*)(slot ? w2 : w1);
    int nv = n >> 2;
    float s = 0.f;
    for (int i = blockIdx.x * blockDim.x + threadIdx.x; i < nv; i += gridDim.x * blockDim.x) {
        float4 v = w4[i];
        s += fabsf(v.x) + fabsf(v.y) + fabsf(v.z) + fabsf(v.w);
    }
    __shared__ float sh[256];
    sh[threadIdx.x] = s;
    __syncthreads();
    for (int o = 128; o > 0; o >>= 1) {
        if (threadIdx.x < o) sh[threadIdx.x] += sh[threadIdx.x + o];
        __syncthreads();
    }
    if (threadIdx.x == 0) g_part[slot][blockIdx.x] = sh[0];
}

__global__ void wfinal(int n) {
    __shared__ float sh[256];
    for (int slot = 0; slot < 2; slot++) {
        sh[threadIdx.x] = g_part[slot][threadIdx.x];
        __syncthreads();
        for (int o = 128; o > 0; o >>= 1) {
            if (threadIdx.x < o) sh[threadIdx.x] += sh[threadIdx.x + o];
            __syncthreads();
        }
        if (threadIdx.x == 0) g_wfac[slot] = fmaxf(sh[0] / (float)n, EPSF);
        __syncthreads();
    }
}

// ---------------- ternary weight quant -> bf16 (both weights) ------------
__global__ void wquant(const float* __restrict__ w1, const float* __restrict__ w2, int n) {
    int slot = blockIdx.y;
    const float* w = slot ? w2 : w1;
    __nv_bfloat16* q = slot ? g_w2q : g_w1q;
    int i = blockIdx.x * blockDim.x + threadIdx.x;
    int nv = n >> 2;
    if (i >= nv) return;
    float sc = 1.f / g_wfac[slot];
    float4 v = ((const float4*)w)[i];
    int t0 = (int)rintf(v.x * sc); t0 = t0 < -1 ? -1 : (t0 > 1 ? 1 : t0);
    int t1 = (int)rintf(v.y * sc); t1 = t1 < -1 ? -1 : (t1 > 1 ? 1 : t1);
    int t2 = (int)rintf(v.z * sc); t2 = t2 < -1 ? -1 : (t2 > 1 ? 1 : t2);
    int t3 = (int)rintf(v.w * sc); t3 = t3 < -1 ? -1 : (t3 > 1 ? 1 : t3);
    __nv_bfloat162* q2 = (__nv_bfloat162*)(q + (size_t)i * 4);
    q2[0] = __nv_bfloat162(__float2bfloat16_rn((float)t0), __float2bfloat16_rn((float)t1));
    q2[1] = __nv_bfloat162(__float2bfloat16_rn((float)t2), __float2bfloat16_rn((float)t3));
}

// ---------------- rmsnorm + absmax int8 quant -> bf16 --------------------
__global__ void act_quant(const float* __restrict__ xin, int slot) {
    const int D = slot ? INNER : DIN;
    const float* X = slot ? g_h : xin;
    __nv_bfloat16* Q = slot ? g_hq : g_xq;
    float* inv = slot ? g_sh : g_sx;

    int m = blockIdx.x;
    const float4* xr = (const float4*)(X + (size_t)m * D);
    int nv = D >> 2;

    float ss = 0.f, am = 0.f;
    for (int v = threadIdx.x; v < nv; v += blockDim.x) {
        float4 f = xr[v];
        ss += f.x * f.x + f.y * f.y + f.z * f.z + f.w * f.w;
        am = fmaxf(am, fmaxf(fmaxf(fabsf(f.x), fabsf(f.y)), fmaxf(fabsf(f.z), fabsf(f.w))));
    }
    __shared__ float shs[256], sha[256];
    shs[threadIdx.x] = ss;
    sha[threadIdx.x] = am;
    __syncthreads();
    for (int o = 128; o > 0; o >>= 1) {
        if (threadIdx.x < o) {
            shs[threadIdx.x] += shs[threadIdx.x + o];
            sha[threadIdx.x] = fmaxf(sha[threadIdx.x], sha[threadIdx.x + o]);
        }
        __syncthreads();
    }
    __shared__ float s_rn, s_sc;
    if (threadIdx.x == 0) {
        float rn = rsqrtf(shs[0] / (float)D + EPSF);
        float amn = fmaxf(sha[0] * rn, EPSF);
        s_rn = rn;
        s_sc = QBF / amn;
        inv[m] = amn / QBF;
    }
    __syncthreads();
    float rn = s_rn, sc = s_sc;

    __nv_bfloat162* qr = (__nv_bfloat162*)(Q + (size_t)m * D);
    for (int v = threadIdx.x; v < nv; v += blockDim.x) {
        float4 f = xr[v];
        int t0 = (int)rintf((f.x * rn) * sc); t0 = t0 < -128 ? -128 : (t0 > 127 ? 127 : t0);
        int t1 = (int)rintf((f.y * rn) * sc); t1 = t1 < -128 ? -128 : (t1 > 127 ? 127 : t1);
        int t2 = (int)rintf((f.z * rn) * sc); t2 = t2 < -128 ? -128 : (t2 > 127 ? 127 : t2);
        int t3 = (int)rintf((f.w * rn) * sc); t3 = t3 < -128 ? -128 : (t3 > 127 ? 127 : t3);
        qr[v * 2 + 0] = __nv_bfloat162(__float2bfloat16_rn((float)t0), __float2bfloat16_rn((float)t1));
        qr[v * 2 + 1] = __nv_bfloat162(__float2bfloat16_rn((float)t2), __float2bfloat16_rn((float)t3));
    }
}

// ---------------- bf16 HMMA GEMM: tile 128x128, K-stage 64 elems ----------
// layer 0: g_h = gelu(xq @ w1q^T * sx*fw1 + b1)   M=MTOK, N=INNER, K=DIN
// layer 1: out =      hq @ w2q^T * sh*fw2 + b2    M=MTOK, N=DIN,   K=INNER
static constexpr int BM = 128, BN = 128, BKE = 64;            // BKE elems = 128 bytes
static constexpr int STAGE_BYTES = (BM + BN) * BKE * 2;       // 32 KB
static constexpr int SMEM_BYTES  = 2 * STAGE_BYTES;           // 64 KB

__device__ __forceinline__ uint32_t swz(uint32_t row, uint32_t kb) {
    return row * 128u + (kb ^ ((row & 7u) << 4));
}

__global__ __launch_bounds__(256)
void gemm_bf16(const float* __restrict__ bias, float* __restrict__ dout, int layer) {
    const __nv_bfloat16 *A, *B;
    const float* inva;
    float* out;
    int N, K;
    if (layer == 0) { A = g_xq; B = g_w1q; inva = g_sx; out = g_h;  N = INNER; K = DIN;  }
    else            { A = g_hq; B = g_w2q; inva = g_sh; out = dout; N = DIN;   K = INNER; }

    extern __shared__ char smem[];
    const uint32_t sb = smem_u32(smem);

    const int tid = threadIdx.x;
    const int wid = tid >> 5, lid = tid & 31;
    const int wm = wid >> 1, wn = wid & 1;        // 4 x 2 warps, each 32m x 64n
    const int m0 = blockIdx.y * BM;
    const int n0 = blockIdx.x * BN;

    float acc[2][8][4];
#pragma unroll
    for (int i = 0; i < 2; i++)
#pragma unroll
        for (int j = 0; j < 8; j++)
#pragma unroll
            for (int q = 0; q < 4; q++) acc[i][j][q] = 0.f;

    const int nk = K / BKE;

    // ldmatrix lane addressing (precompute row*128 and xor term)
    const int ltile = lid >> 3, lr = lid & 7;
    uint32_t a_off[2], a_xor[2];
    const uint32_t a_kadd = (ltile >> 1) * 16;    // bytes
#pragma unroll
    for (int i = 0; i < 2; i++) {
        uint32_t row = wm * 32 + i * 16 + (ltile & 1) * 8 + lr;
        a_off[i] = row * 128u;
        a_xor[i] = (row & 7u) << 4;
    }
    uint32_t b_off[4], b_xor[4];
    const uint32_t b_kadd = (ltile & 1) * 16;
#pragma unroll
    for (int jb = 0; jb < 4; jb++) {
        uint32_t row = wn * 64 + jb * 16 + (ltile >> 1) * 8 + lr;
        b_off[jb] = row * 128u;
        b_xor[jb] = (row & 7u) << 4;
    }

    auto load_stage = [&](int buf, int c) {
        uint32_t baseA = sb + buf * STAGE_BYTES;
        uint32_t baseB = baseA + BM * BKE * 2;
        const __nv_bfloat16* Ap = A + (size_t)m0 * K + c * BKE;
        const __nv_bfloat16* Bp = B + (size_t)n0 * K + c * BKE;
#pragma unroll
        for (int t = 0; t < 4; t++) {
            int ci = tid + t * 256;                // 1024 chunks of 16B
            uint32_t row = ci >> 3, ch = (ci & 7) * 16;
            cp_async16(baseA + swz(row, ch), Ap + (size_t)row * K + (ci & 7) * 8);
        }
#pragma unroll
        for (int t = 0; t < 4; t++) {
            int ci = tid + t * 256;
            uint32_t row = ci >> 3, ch = (ci & 7) * 16;
            cp_async16(baseB + swz(row, ch), Bp + (size_t)row * K + (ci & 7) * 8);
        }
        CP_COMMIT();
    };

    load_stage(0, 0);

    for (int c = 0; c < nk; c++) {
        if (c + 1 < nk) {
            load_stage((c + 1) & 1, c + 1);
            CP_WAIT(1);
        } else {
            CP_WAIT(0);
        }
        __syncthreads();

        uint32_t baseA = sb + (c & 1) * STAGE_BYTES;
        uint32_t baseB = baseA + BM * BKE * 2;

#pragma unroll
        for (int ks = 0; ks < 4; ks++) {           // 4 x k16
            uint32_t kbA = ks * 32 + a_kadd;
            uint32_t kbB = ks * 32 + b_kadd;
            uint32_t afr[2][4];
#pragma unroll
            for (int i = 0; i < 2; i++)
                ldmx4(afr[i][0], afr[i][1], afr[i][2], afr[i][3],
                      baseA + a_off[i] + (kbA ^ a_xor[i]));
            uint32_t bfr[8][2];
#pragma unroll
            for (int jb = 0; jb < 4; jb++) {
                uint32_t r0, r1, r2, r3;
                ldmx4(r0, r1, r2, r3, baseB + b_off[jb] + (kbB ^ b_xor[jb]));
                bfr[jb * 2 + 0][0] = r0; bfr[jb * 2 + 0][1] = r1;
                bfr[jb * 2 + 1][0] = r2; bfr[jb * 2 + 1][1] = r3;
            }
#pragma unroll
            for (int i = 0; i < 2; i++)
#pragma unroll
                for (int j = 0; j < 8; j++)
                    mma_bf16(acc[i][j], afr[i], bfr[j]);
        }
        __syncthreads();
    }

    // ----- epilogue: dequant + bias (+ exact gelu for layer 0) -----
    const float fw = g_wfac[layer];
    const int g = lid >> 2, tig = lid & 3;
#pragma unroll
    for (int i = 0; i < 2; i++) {
        int r0 = m0 + wm * 32 + i * 16 + g;
        float fa0 = inva[r0] * fw;
        float fa1 = inva[r0 + 8] * fw;
#pragma unroll
        for (int j = 0; j < 8; j++) {
            int n = n0 + wn * 64 + j * 8 + tig * 2;
            float bx = bias[n], by = bias[n + 1];
            float v0 = acc[i][j][0] * fa0 + bx;
            float v1 = acc[i][j][1] * fa0 + by;
            float v2 = acc[i][j][2] * fa1 + bx;
            float v3 = acc[i][j][3] * fa1 + by;
            if (layer == 0) {
                v0 = 0.5f * v0 * (1.f + erff(v0 * 0.70710678118654752f));
                v1 = 0.5f * v1 * (1.f + erff(v1 * 0.70710678118654752f));
                v2 = 0.5f * v2 * (1.f + erff(v2 * 0.70710678118654752f));
                v3 = 0.5f * v3 * (1.f + erff(v3 * 0.70710678118654752f));
            }
            *(float2*)(out + (size_t)r0 * N + n)       = make_float2(v0, v1);
            *(float2*)(out + (size_t)(r0 + 8) * N + n) = make_float2(v2, v3);
        }
    }
}

// -------------------------------------------------------------------------
extern "C" void kernel_launch(void* const* d_in, const int* in_sizes, int n_in,
                              void* d_out, int out_size) {
    const float* x  = (const float*)d_in[0];
    const float* w1 = (const float*)d_in[1];
    const float* b1 = (const float*)d_in[2];
    const float* w2 = (const float*)d_in[3];
    const float* b2 = (const float*)d_in[4];
    float* out = (float*)d_out;

    const int n = INNER * DIN;   // both weights have the same element count

    cudaFuncSetAttribute(gemm_bf16, cudaFuncAttributeMaxDynamicSharedMemorySize, SMEM_BYTES);

    // launch order chosen so gemm_bf16(layer 0) lands in the ncu capture window
    wabs_part<<<dim3(256, 2), 256>>>(w1, w2, n);                 // 0
    wfinal<<<1, 256>>>(n);                                       // 1
    wquant<<<dim3(n / 4 / 256, 2), 256>>>(w1, w2, n);            // 2
    act_quant<<<MTOK, 256>>>(x, 0);                              // 3
    gemm_bf16<<<dim3(INNER / BN, MTOK / BM), 256, SMEM_BYTES>>>(b1, nullptr, 0);  // 4
    act_quant<<<MTOK, 256>>>(nullptr, 1);                        // 5
    gemm_bf16<<<dim3(DIN / BN, MTOK / BM), 256, SMEM_BYTES>>>(b2, out, 1);        // 6
}